// round 8
// baseline (speedup 1.0000x reference)
#include <cuda_runtime.h>
#include <mma.h>
#include <cstdint>
using namespace nvcuda;

#define SEQ   4096
#define IND   1024
#define TD    3072   // 3 * 1024
#define DHEAD 1024

// Scratch (allocation-free rule: __device__ globals)
__device__ float g_qvk[SEQ * TD];        // [S,3D]: [0,1024)=Q, [1024,2048)=V, [2048,3072)=K
__device__ float g_S[(size_t)SEQ * SEQ]; // scores -> probabilities in-place

constexpr int BM = 128, BN = 128, BK = 32;
constexpr int NTHREADS = 512;            // 16 warps, 4x4 warp grid, 32x32 warp tile
constexpr int STAGES = 3;
constexpr int LDA   = 36;    // padded stride for [x][32] tiles (A and transposed-B)
constexpr int LDBNN = 136;   // padded stride for [32][128] tiles (row-major B)
constexpr int STG   = 4608;  // floats per stage buffer (128*36 >= 32*136)
constexpr int SMEM_BYTES = 2 * STAGES * STG * 4;  // 110,592 B

// ---------------- cp.async helpers ----------------
__device__ __forceinline__ void cp16(void* dst, const void* src) {
    uint32_t d = (uint32_t)__cvta_generic_to_shared(dst);
    asm volatile("cp.async.cg.shared.global [%0], [%1], 16;\n" :: "r"(d), "l"(src));
}
__device__ __forceinline__ void cp_commit() {
    asm volatile("cp.async.commit_group;\n");
}

// ---------------- tile loaders (async) ----------------
// A tile: BM x BK  -> As[r*LDA + c]
// B tile (BT=false, row-major [K][N]): BK x BN -> Bs[k*LDBNN + n]
// B tile (BT=true,  B is [N][K] row-major): BN x BK -> Bs[n*LDA + k]  (col-major frag)
template<bool BT>
__device__ __forceinline__ void load_tiles(float* As, float* Bs,
    const float* A, int lda, const float* B, int ldb,
    int m0, int n0, int k0)
{
    const int tid = threadIdx.x;
#pragma unroll
    for (int t = 0; t < 2; t++) {
        int idx = tid + t * NTHREADS;
        int r = idx >> 3, c = (idx & 7) << 2;     // 8 float4 per 32-wide row
        cp16(&As[r * LDA + c], &A[(size_t)(m0 + r) * lda + k0 + c]);
    }
    if (BT) {
#pragma unroll
        for (int t = 0; t < 2; t++) {
            int idx = tid + t * NTHREADS;
            int r = idx >> 3, c = (idx & 7) << 2;
            cp16(&Bs[r * LDA + c], &B[(size_t)(n0 + r) * ldb + k0 + c]);
        }
    } else {
#pragma unroll
        for (int t = 0; t < 2; t++) {
            int idx = tid + t * NTHREADS;
            int r = idx >> 5, c = (idx & 31) << 2; // 32 float4 per 128-wide row
            cp16(&Bs[r * LDBNN + c], &B[(size_t)(k0 + r) * ldb + n0 + c]);
        }
    }
}

// ---------------- per-warp tf32 MMA on a staged tile (32x32 warp tile) ----------------
template<bool BT>
__device__ __forceinline__ void mma_stage(const float* As, const float* Bs,
    wmma::fragment<wmma::accumulator, 16, 16, 8, float> (&c)[2][2],
    int wm, int wn)
{
#pragma unroll
    for (int kt = 0; kt < BK / 8; kt++) {
        wmma::fragment<wmma::matrix_a, 16, 16, 8, wmma::precision::tf32, wmma::row_major> a[2];
#pragma unroll
        for (int i = 0; i < 2; i++) {
            wmma::load_matrix_sync(a[i], &As[(wm * 32 + i * 16) * LDA + kt * 8], LDA);
#pragma unroll
            for (int t = 0; t < a[i].num_elements; t++)
                a[i].x[t] = wmma::__float_to_tf32(a[i].x[t]);
        }
        if constexpr (BT) {
            wmma::fragment<wmma::matrix_b, 16, 16, 8, wmma::precision::tf32, wmma::col_major> b[2];
#pragma unroll
            for (int j = 0; j < 2; j++) {
                wmma::load_matrix_sync(b[j], &Bs[(wn * 32 + j * 16) * LDA + kt * 8], LDA);
#pragma unroll
                for (int t = 0; t < b[j].num_elements; t++)
                    b[j].x[t] = wmma::__float_to_tf32(b[j].x[t]);
            }
#pragma unroll
            for (int i = 0; i < 2; i++)
#pragma unroll
                for (int j = 0; j < 2; j++)
                    wmma::mma_sync(c[i][j], a[i], b[j], c[i][j]);
        } else {
            wmma::fragment<wmma::matrix_b, 16, 16, 8, wmma::precision::tf32, wmma::row_major> b[2];
#pragma unroll
            for (int j = 0; j < 2; j++) {
                wmma::load_matrix_sync(b[j], &Bs[(kt * 8) * LDBNN + wn * 32 + j * 16], LDBNN);
#pragma unroll
                for (int t = 0; t < b[j].num_elements; t++)
                    b[j].x[t] = wmma::__float_to_tf32(b[j].x[t]);
            }
#pragma unroll
            for (int i = 0; i < 2; i++)
#pragma unroll
                for (int j = 0; j < 2; j++)
                    wmma::mma_sync(c[i][j], a[i], b[j], c[i][j]);
        }
    }
}

// ---------------- 3-stage pipelined 128x128x32 tf32 GEMM, one barrier/iter ----------------
// BT: B is [N][K] row-major (col-major fragments)   -- for Q@K^T
// CSKIP: skip blocks fully above the diagonal       -- for Q@K^T
// CK: truncate K to (by+1)*BM                       -- for P@V
template<bool BT, bool CSKIP, bool CK>
__global__ void __launch_bounds__(NTHREADS, 1)
gemm_tf32(const float* __restrict__ A, int lda,
          const float* __restrict__ B, int ldb,
          float* __restrict__ C, int ldc, int K)
{
    const int bx = blockIdx.x, by = blockIdx.y;
    if (CSKIP && bx > by) return;

    extern __shared__ float smem[];
    float* Ast[STAGES]; float* Bst[STAGES];
#pragma unroll
    for (int s = 0; s < STAGES; s++) {
        Ast[s] = smem + s * STG;
        Bst[s] = smem + (STAGES + s) * STG;
    }

    const int m0 = by * BM, n0 = bx * BN;
    const int Keff = CK ? (by + 1) * BM : K;
    const int NK = Keff / BK;

    wmma::fragment<wmma::accumulator, 16, 16, 8, float> c[2][2];
#pragma unroll
    for (int i = 0; i < 2; i++)
#pragma unroll
        for (int j = 0; j < 2; j++)
            wmma::fill_fragment(c[i][j], 0.0f);

    const int warp = threadIdx.x >> 5;
    const int wm = warp >> 2, wn = warp & 3;  // 4x4 warps, 32x32 per-warp tile

    // Prologue: prefetch stages 0 and 1
    load_tiles<BT>(Ast[0], Bst[0], A, lda, B, ldb, m0, n0, 0);
    cp_commit();
    if (NK > 1) {
        load_tiles<BT>(Ast[1], Bst[1], A, lda, B, ldb, m0, n0, BK);
        cp_commit();
    }

    for (int kb = 0; kb < NK; kb++) {
        if (kb + 2 < NK) {
            asm volatile("cp.async.wait_group 1;\n");
            __syncthreads();   // stage kb ready; all warps done with stage (kb+2)%STAGES (=kb-1)
            load_tiles<BT>(Ast[(kb + 2) % STAGES], Bst[(kb + 2) % STAGES],
                           A, lda, B, ldb, m0, n0, (kb + 2) * BK);
            cp_commit();
        } else {
            asm volatile("cp.async.wait_group 0;\n");
            __syncthreads();
        }
        mma_stage<BT>(Ast[kb % STAGES], Bst[kb % STAGES], c, wm, wn);
    }

#pragma unroll
    for (int i = 0; i < 2; i++)
#pragma unroll
        for (int j = 0; j < 2; j++)
            wmma::store_matrix_sync(
                &C[(size_t)(m0 + wm * 32 + i * 16) * ldc + n0 + wn * 32 + j * 16],
                c[i][j], ldc, wmma::mem_row_major);
}

// ---------------- row softmax in-place; zero-fill to 128-block boundary ----------------
__global__ void __launch_bounds__(256)
softmax_kernel()
{
    const int i = blockIdx.x;
    float* row = g_S + (size_t)i * SEQ;
    const int n = i + 1;
    const float scale = 0.03125f;   // 1/sqrt(1024)
    __shared__ float red[256];

    float m = -1e30f;
    for (int j = threadIdx.x; j < n; j += 256) m = fmaxf(m, row[j] * scale);
    red[threadIdx.x] = m; __syncthreads();
    for (int s = 128; s > 0; s >>= 1) {
        if (threadIdx.x < s) red[threadIdx.x] = fmaxf(red[threadIdx.x], red[threadIdx.x + s]);
        __syncthreads();
    }
    m = red[0]; __syncthreads();

    float sum = 0.0f;
    for (int j = threadIdx.x; j < n; j += 256) sum += __expf(row[j] * scale - m);
    red[threadIdx.x] = sum; __syncthreads();
    for (int s = 128; s > 0; s >>= 1) {
        if (threadIdx.x < s) red[threadIdx.x] += red[threadIdx.x + s];
        __syncthreads();
    }
    sum = red[0];
    const float inv = 1.0f / sum;

    const int zend = ((i >> 7) + 1) << 7;   // end of this row's 128-row block
    for (int j = threadIdx.x; j < zend; j += 256)
        row[j] = (j < n) ? __expf(row[j] * scale - m) * inv : 0.0f;
}

extern "C" void kernel_launch(void* const* d_in, const int* in_sizes, int n_in,
                              void* d_out, int out_size)
{
    const float* x = (const float*)d_in[0];   // [4096, 1024]
    const float* W = (const float*)d_in[1];   // [1024, 3072]
    float* out = (float*)d_out;               // [4096, 1024]

    float* qvk; cudaGetSymbolAddress((void**)&qvk, g_qvk);
    float* S;   cudaGetSymbolAddress((void**)&S, g_S);

    // Opt in to >48KB dynamic smem (host-side, idempotent, capture-safe)
    cudaFuncSetAttribute(gemm_tf32<false, false, false>,
                         cudaFuncAttributeMaxDynamicSharedMemorySize, SMEM_BYTES);
    cudaFuncSetAttribute(gemm_tf32<true, true, false>,
                         cudaFuncAttributeMaxDynamicSharedMemorySize, SMEM_BYTES);
    cudaFuncSetAttribute(gemm_tf32<false, false, true>,
                         cudaFuncAttributeMaxDynamicSharedMemorySize, SMEM_BYTES);

    // 1) qvk = x @ W            [4096,1024] @ [1024,3072]
    {
        dim3 grid(TD / BN, SEQ / BM);
        gemm_tf32<false, false, false><<<grid, NTHREADS, SMEM_BYTES>>>(
            x, IND, W, TD, qvk, TD, IND);
    }
    // 2) S = Q @ K^T (raw scores; scale folded into softmax), lower-tri blocks only
    {
        dim3 grid(SEQ / BN, SEQ / BM);
        gemm_tf32<true, true, false><<<grid, NTHREADS, SMEM_BYTES>>>(
            qvk /*Q*/, TD, qvk + 2048 /*K*/, TD, S, SEQ, DHEAD);
    }
    // 3) softmax rows in-place (zero-fills masked cols up to 128-block boundary)
    softmax_kernel<<<SEQ, 256>>>();
    // 4) out = P @ V with causal K truncation per row-block
    {
        dim3 grid(DHEAD / BN, SEQ / BM);
        gemm_tf32<false, false, true><<<grid, NTHREADS, SMEM_BYTES>>>(
            S, SEQ, qvk + 1024 /*V*/, TD, out, DHEAD, SEQ);
    }
}

// round 14
// speedup vs baseline: 1.0328x; 1.0328x over previous
#include <cuda_runtime.h>
#include <mma.h>
#include <cstdint>
using namespace nvcuda;

#define SEQ   4096
#define IND   1024
#define TD    3072   // 3 * 1024
#define DHEAD 1024

// Scratch (allocation-free rule: __device__ globals)
__device__ float g_qvk[SEQ * TD];        // [S,3D]: [0,1024)=Q, [1024,2048)=V, [2048,3072)=K
__device__ float g_S[(size_t)SEQ * SEQ]; // scores -> probabilities in-place

constexpr int BM = 128, BN = 128, BK = 32;
constexpr int NTHREADS = 256;            // 8 warps: 4x2 grid of 32x64 warp tiles
constexpr int STAGES = 3;
constexpr int LDA   = 36;    // padded stride for [x][32] tiles (A and transposed-B)
constexpr int LDBNN = 136;   // padded stride for [32][128] tiles (row-major B)
constexpr int STG   = 4608;  // floats per stage buffer (128*36 >= 32*136)
constexpr int SMEM_BYTES = 2 * STAGES * STG * 4;  // 110,592 B

// ---------------- cp.async helpers ----------------
__device__ __forceinline__ void cp16(void* dst, const void* src) {
    uint32_t d = (uint32_t)__cvta_generic_to_shared(dst);
    asm volatile("cp.async.cg.shared.global [%0], [%1], 16;\n" :: "r"(d), "l"(src));
}
__device__ __forceinline__ void cp_commit() {
    asm volatile("cp.async.commit_group;\n");
}

// ---------------- tile loaders (async) ----------------
// A tile: BM x BK  -> As[r*LDA + c]
// B tile (BT=false, row-major [K][N]): BK x BN -> Bs[k*LDBNN + n]
// B tile (BT=true,  B is [N][K] row-major): BN x BK -> Bs[n*LDA + k]  (col-major frag)
template<bool BT>
__device__ __forceinline__ void load_tiles(float* As, float* Bs,
    const float* A, int lda, const float* B, int ldb,
    int m0, int n0, int k0)
{
    const int tid = threadIdx.x;
#pragma unroll
    for (int t = 0; t < 4; t++) {
        int idx = tid + t * NTHREADS;
        int r = idx >> 3, c = (idx & 7) << 2;     // 8 float4 per 32-wide row
        cp16(&As[r * LDA + c], &A[(size_t)(m0 + r) * lda + k0 + c]);
    }
    if (BT) {
#pragma unroll
        for (int t = 0; t < 4; t++) {
            int idx = tid + t * NTHREADS;
            int r = idx >> 3, c = (idx & 7) << 2;
            cp16(&Bs[r * LDA + c], &B[(size_t)(n0 + r) * ldb + k0 + c]);
        }
    } else {
#pragma unroll
        for (int t = 0; t < 4; t++) {
            int idx = tid + t * NTHREADS;
            int r = idx >> 5, c = (idx & 31) << 2; // 32 float4 per 128-wide row
            cp16(&Bs[r * LDBNN + c], &B[(size_t)(k0 + r) * ldb + n0 + c]);
        }
    }
}

// ---------------- per-warp tf32 MMA on a staged tile (32x64 warp tile) ----------------
template<bool BT>
__device__ __forceinline__ void mma_stage(const float* As, const float* Bs,
    wmma::fragment<wmma::accumulator, 16, 16, 8, float> (&c)[2][4],
    int wm, int wn)
{
#pragma unroll
    for (int kt = 0; kt < BK / 8; kt++) {
        wmma::fragment<wmma::matrix_a, 16, 16, 8, wmma::precision::tf32, wmma::row_major> a[2];
#pragma unroll
        for (int i = 0; i < 2; i++) {
            wmma::load_matrix_sync(a[i], &As[(wm * 32 + i * 16) * LDA + kt * 8], LDA);
#pragma unroll
            for (int t = 0; t < a[i].num_elements; t++)
                a[i].x[t] = wmma::__float_to_tf32(a[i].x[t]);
        }
        if constexpr (BT) {
            wmma::fragment<wmma::matrix_b, 16, 16, 8, wmma::precision::tf32, wmma::col_major> b[4];
#pragma unroll
            for (int j = 0; j < 4; j++) {
                wmma::load_matrix_sync(b[j], &Bs[(wn * 64 + j * 16) * LDA + kt * 8], LDA);
#pragma unroll
                for (int t = 0; t < b[j].num_elements; t++)
                    b[j].x[t] = wmma::__float_to_tf32(b[j].x[t]);
            }
#pragma unroll
            for (int i = 0; i < 2; i++)
#pragma unroll
                for (int j = 0; j < 4; j++)
                    wmma::mma_sync(c[i][j], a[i], b[j], c[i][j]);
        } else {
            wmma::fragment<wmma::matrix_b, 16, 16, 8, wmma::precision::tf32, wmma::row_major> b[4];
#pragma unroll
            for (int j = 0; j < 4; j++) {
                wmma::load_matrix_sync(b[j], &Bs[(kt * 8) * LDBNN + wn * 64 + j * 16], LDBNN);
#pragma unroll
                for (int t = 0; t < b[j].num_elements; t++)
                    b[j].x[t] = wmma::__float_to_tf32(b[j].x[t]);
            }
#pragma unroll
            for (int i = 0; i < 2; i++)
#pragma unroll
                for (int j = 0; j < 4; j++)
                    wmma::mma_sync(c[i][j], a[i], b[j], c[i][j]);
        }
    }
}

// ---------------- 3-stage pipelined 128x128x32 tf32 GEMM, ONE barrier per k-iter ----------------
// BT: B is [N][K] row-major (col-major fragments)   -- for Q@K^T
// CSKIP: skip blocks fully above the diagonal       -- for Q@K^T
// CK: truncate K to (by+1)*BM                       -- for P@V
template<bool BT, bool CSKIP, bool CK>
__global__ void __launch_bounds__(NTHREADS, 1)
gemm_tf32(const float* __restrict__ A, int lda,
          const float* __restrict__ B, int ldb,
          float* __restrict__ C, int ldc, int K)
{
    const int bx = blockIdx.x, by = blockIdx.y;
    if (CSKIP && bx > by) return;

    extern __shared__ float smem[];
    float* Ast[STAGES]; float* Bst[STAGES];
#pragma unroll
    for (int s = 0; s < STAGES; s++) {
        Ast[s] = smem + s * STG;
        Bst[s] = smem + (STAGES + s) * STG;
    }

    const int m0 = by * BM, n0 = bx * BN;
    const int Keff = CK ? (by + 1) * BM : K;
    const int NK = Keff / BK;

    wmma::fragment<wmma::accumulator, 16, 16, 8, float> c[2][4];
#pragma unroll
    for (int i = 0; i < 2; i++)
#pragma unroll
        for (int j = 0; j < 4; j++)
            wmma::fill_fragment(c[i][j], 0.0f);

    const int warp = threadIdx.x >> 5;
    const int wm = warp >> 1, wn = warp & 1;  // 4x2 warps, 32x64 per-warp tile

    // Prologue: prefetch stages 0 and 1
    load_tiles<BT>(Ast[0], Bst[0], A, lda, B, ldb, m0, n0, 0);
    cp_commit();
    if (NK > 1) {
        load_tiles<BT>(Ast[1], Bst[1], A, lda, B, ldb, m0, n0, BK);
        cp_commit();
    }

    for (int kb = 0; kb < NK; kb++) {
        if (kb + 1 < NK) asm volatile("cp.async.wait_group 1;\n");
        else             asm volatile("cp.async.wait_group 0;\n");
        // Single barrier: stage kb is resident for everyone, and every warp has
        // finished mma(kb-1) on stage (kb-1)%3 == (kb+2)%3, so it may be refilled.
        __syncthreads();
        if (kb + 2 < NK) {
            load_tiles<BT>(Ast[(kb + 2) % STAGES], Bst[(kb + 2) % STAGES],
                           A, lda, B, ldb, m0, n0, (kb + 2) * BK);
            cp_commit();
        }
        mma_stage<BT>(Ast[kb % STAGES], Bst[kb % STAGES], c, wm, wn);
    }

#pragma unroll
    for (int i = 0; i < 2; i++)
#pragma unroll
        for (int j = 0; j < 4; j++)
            wmma::store_matrix_sync(
                &C[(size_t)(m0 + wm * 32 + i * 16) * ldc + n0 + wn * 64 + j * 16],
                c[i][j], ldc, wmma::mem_row_major);
}

// ---------------- row softmax in-place; zero-fill to 128-block boundary ----------------
__global__ void __launch_bounds__(256)
softmax_kernel()
{
    const int i = blockIdx.x;
    float* row = g_S + (size_t)i * SEQ;
    const int n = i + 1;
    const float scale = 0.03125f;   // 1/sqrt(1024)
    __shared__ float red[256];

    float m = -1e30f;
    for (int j = threadIdx.x; j < n; j += 256) m = fmaxf(m, row[j] * scale);
    red[threadIdx.x] = m; __syncthreads();
    for (int s = 128; s > 0; s >>= 1) {
        if (threadIdx.x < s) red[threadIdx.x] = fmaxf(red[threadIdx.x], red[threadIdx.x + s]);
        __syncthreads();
    }
    m = red[0]; __syncthreads();

    // Pass 2: compute exp once, store it, accumulate sum
    float sum = 0.0f;
    for (int j = threadIdx.x; j < n; j += 256) {
        float e = __expf(row[j] * scale - m);
        row[j] = e;
        sum += e;
    }
    red[threadIdx.x] = sum; __syncthreads();
    for (int s = 128; s > 0; s >>= 1) {
        if (threadIdx.x < s) red[threadIdx.x] += red[threadIdx.x + s];
        __syncthreads();
    }
    sum = red[0];
    const float inv = 1.0f / sum;

    // Pass 3: normalize; zero-fill masked cols up to this row's 128-block boundary
    const int zend = ((i >> 7) + 1) << 7;
    for (int j = threadIdx.x; j < zend; j += 256)
        row[j] = (j < n) ? row[j] * inv : 0.0f;
}

extern "C" void kernel_launch(void* const* d_in, const int* in_sizes, int n_in,
                              void* d_out, int out_size)
{
    const float* x = (const float*)d_in[0];   // [4096, 1024]
    const float* W = (const float*)d_in[1];   // [1024, 3072]
    float* out = (float*)d_out;               // [4096, 1024]

    float* qvk; cudaGetSymbolAddress((void**)&qvk, g_qvk);
    float* S;   cudaGetSymbolAddress((void**)&S, g_S);

    // Opt in to >48KB dynamic smem (host-side, idempotent, capture-safe)
    cudaFuncSetAttribute(gemm_tf32<false, false, false>,
                         cudaFuncAttributeMaxDynamicSharedMemorySize, SMEM_BYTES);
    cudaFuncSetAttribute(gemm_tf32<true, true, false>,
                         cudaFuncAttributeMaxDynamicSharedMemorySize, SMEM_BYTES);
    cudaFuncSetAttribute(gemm_tf32<false, false, true>,
                         cudaFuncAttributeMaxDynamicSharedMemorySize, SMEM_BYTES);

    // 1) qvk = x @ W            [4096,1024] @ [1024,3072]
    {
        dim3 grid(TD / BN, SEQ / BM);
        gemm_tf32<false, false, false><<<grid, NTHREADS, SMEM_BYTES>>>(
            x, IND, W, TD, qvk, TD, IND);
    }
    // 2) S = Q @ K^T (raw scores; scale folded into softmax), lower-tri blocks only
    {
        dim3 grid(SEQ / BN, SEQ / BM);
        gemm_tf32<true, true, false><<<grid, NTHREADS, SMEM_BYTES>>>(
            qvk /*Q*/, TD, qvk + 2048 /*K*/, TD, S, SEQ, DHEAD);
    }
    // 3) softmax rows in-place (zero-fills masked cols up to 128-block boundary)
    softmax_kernel<<<SEQ, 256>>>();
    // 4) out = P @ V with causal K truncation per row-block
    {
        dim3 grid(DHEAD / BN, SEQ / BM);
        gemm_tf32<false, false, true><<<grid, NTHREADS, SMEM_BYTES>>>(
            S, SEQ, qvk + 1024 /*V*/, TD, out, DHEAD, SEQ);
    }
}

// round 15
// speedup vs baseline: 1.1440x; 1.1078x over previous
#include <cuda_runtime.h>
#include <mma.h>
#include <cstdint>
using namespace nvcuda;

#define SEQ   4096
#define IND   1024
#define TD    3072   // 3 * 1024
#define DHEAD 1024

// Scratch (allocation-free rule: __device__ globals)
__device__ float g_qvk[SEQ * TD];        // [S,3D]: [0,1024)=Q, [1024,2048)=V, [2048,3072)=K  (tf32-rounded)
__device__ float g_S[(size_t)SEQ * SEQ]; // scores -> probabilities in-place (tf32-rounded after softmax)
__device__ float g_xr[SEQ * IND];        // x rounded to tf32
__device__ float g_Wr[IND * TD];         // W rounded to tf32

constexpr int BM = 128, BN = 128, BK = 32;
constexpr int NTHREADS = 256;            // 8 warps: 4x2 grid of 32x64 warp tiles
constexpr int STAGES = 3;
constexpr int LDA   = 36;    // padded stride for [x][32] tiles (A and transposed-B)
constexpr int LDBNN = 136;   // padded stride for [32][128] tiles (row-major B)
constexpr int STG   = 4608;  // floats per stage buffer (128*36 >= 32*136)
constexpr int SMEM_BYTES = 2 * STAGES * STG * 4;  // 110,592 B

// ---------------- tf32 rounding (round-to-nearest, same as wmma::__float_to_tf32) ----
__device__ __forceinline__ float tf32_rna(float v) {
    float r;
    asm("cvt.rna.tf32.f32 %0, %1;" : "=f"(r) : "f"(v));
    return r;
}

// ---------------- cp.async helpers ----------------
__device__ __forceinline__ void cp16(void* dst, const void* src) {
    uint32_t d = (uint32_t)__cvta_generic_to_shared(dst);
    asm volatile("cp.async.cg.shared.global [%0], [%1], 16;\n" :: "r"(d), "l"(src));
}
__device__ __forceinline__ void cp_commit() {
    asm volatile("cp.async.commit_group;\n");
}

// ---------------- tile loaders (async) ----------------
// A tile: BM x BK  -> As[r*LDA + c]
// B tile (BT=false, row-major [K][N]): BK x BN -> Bs[k*LDBNN + n]
// B tile (BT=true,  B is [N][K] row-major): BN x BK -> Bs[n*LDA + k]  (col-major frag)
template<bool BT>
__device__ __forceinline__ void load_tiles(float* As, float* Bs,
    const float* A, int lda, const float* B, int ldb,
    int m0, int n0, int k0)
{
    const int tid = threadIdx.x;
#pragma unroll
    for (int t = 0; t < 4; t++) {
        int idx = tid + t * NTHREADS;
        int r = idx >> 3, c = (idx & 7) << 2;     // 8 float4 per 32-wide row
        cp16(&As[r * LDA + c], &A[(size_t)(m0 + r) * lda + k0 + c]);
    }
    if (BT) {
#pragma unroll
        for (int t = 0; t < 4; t++) {
            int idx = tid + t * NTHREADS;
            int r = idx >> 3, c = (idx & 7) << 2;
            cp16(&Bs[r * LDA + c], &B[(size_t)(n0 + r) * ldb + k0 + c]);
        }
    } else {
#pragma unroll
        for (int t = 0; t < 4; t++) {
            int idx = tid + t * NTHREADS;
            int r = idx >> 5, c = (idx & 31) << 2; // 32 float4 per 128-wide row
            cp16(&Bs[r * LDBNN + c], &B[(size_t)(k0 + r) * ldb + n0 + c]);
        }
    }
}

// ---------------- per-warp tf32 MMA on a staged tile (32x64 warp tile) ----------------
// Operands in SMEM are ALREADY tf32-rounded -> no per-fragment conversion needed.
template<bool BT>
__device__ __forceinline__ void mma_stage(const float* As, const float* Bs,
    wmma::fragment<wmma::accumulator, 16, 16, 8, float> (&c)[2][4],
    int wm, int wn)
{
#pragma unroll
    for (int kt = 0; kt < BK / 8; kt++) {
        wmma::fragment<wmma::matrix_a, 16, 16, 8, wmma::precision::tf32, wmma::row_major> a[2];
#pragma unroll
        for (int i = 0; i < 2; i++)
            wmma::load_matrix_sync(a[i], &As[(wm * 32 + i * 16) * LDA + kt * 8], LDA);
        if constexpr (BT) {
            wmma::fragment<wmma::matrix_b, 16, 16, 8, wmma::precision::tf32, wmma::col_major> b[4];
#pragma unroll
            for (int j = 0; j < 4; j++)
                wmma::load_matrix_sync(b[j], &Bs[(wn * 64 + j * 16) * LDA + kt * 8], LDA);
#pragma unroll
            for (int i = 0; i < 2; i++)
#pragma unroll
                for (int j = 0; j < 4; j++)
                    wmma::mma_sync(c[i][j], a[i], b[j], c[i][j]);
        } else {
            wmma::fragment<wmma::matrix_b, 16, 16, 8, wmma::precision::tf32, wmma::row_major> b[4];
#pragma unroll
            for (int j = 0; j < 4; j++)
                wmma::load_matrix_sync(b[j], &Bs[(kt * 8) * LDBNN + wn * 64 + j * 16], LDBNN);
#pragma unroll
            for (int i = 0; i < 2; i++)
#pragma unroll
                for (int j = 0; j < 4; j++)
                    wmma::mma_sync(c[i][j], a[i], b[j], c[i][j]);
        }
    }
}

// ---------------- 3-stage pipelined 128x128x32 tf32 GEMM, ONE barrier per k-iter ----------------
// BT: B is [N][K] row-major (col-major fragments)   -- for Q@K^T
// CSKIP: skip blocks fully above the diagonal       -- for Q@K^T
// CK: truncate K to (by+1)*BM                       -- for P@V
// RC: round the output accumulators to tf32 on store -- for GEMM1 (Q/K/V become pre-rounded)
template<bool BT, bool CSKIP, bool CK, bool RC>
__global__ void __launch_bounds__(NTHREADS, 1)
gemm_tf32(const float* __restrict__ A, int lda,
          const float* __restrict__ B, int ldb,
          float* __restrict__ C, int ldc, int K)
{
    const int bx = blockIdx.x, by = blockIdx.y;
    if (CSKIP && bx > by) return;

    extern __shared__ float smem[];
    float* Ast[STAGES]; float* Bst[STAGES];
#pragma unroll
    for (int s = 0; s < STAGES; s++) {
        Ast[s] = smem + s * STG;
        Bst[s] = smem + (STAGES + s) * STG;
    }

    const int m0 = by * BM, n0 = bx * BN;
    const int Keff = CK ? (by + 1) * BM : K;
    const int NK = Keff / BK;

    wmma::fragment<wmma::accumulator, 16, 16, 8, float> c[2][4];
#pragma unroll
    for (int i = 0; i < 2; i++)
#pragma unroll
        for (int j = 0; j < 4; j++)
            wmma::fill_fragment(c[i][j], 0.0f);

    const int warp = threadIdx.x >> 5;
    const int wm = warp >> 1, wn = warp & 1;  // 4x2 warps, 32x64 per-warp tile

    // Prologue: prefetch stages 0 and 1
    load_tiles<BT>(Ast[0], Bst[0], A, lda, B, ldb, m0, n0, 0);
    cp_commit();
    if (NK > 1) {
        load_tiles<BT>(Ast[1], Bst[1], A, lda, B, ldb, m0, n0, BK);
        cp_commit();
    }

    for (int kb = 0; kb < NK; kb++) {
        if (kb + 1 < NK) asm volatile("cp.async.wait_group 1;\n");
        else             asm volatile("cp.async.wait_group 0;\n");
        // Single barrier: stage kb is resident for everyone, and every warp has
        // finished mma(kb-1) on stage (kb-1)%3 == (kb+2)%3, so it may be refilled.
        __syncthreads();
        if (kb + 2 < NK) {
            load_tiles<BT>(Ast[(kb + 2) % STAGES], Bst[(kb + 2) % STAGES],
                           A, lda, B, ldb, m0, n0, (kb + 2) * BK);
            cp_commit();
        }
        mma_stage<BT>(Ast[kb % STAGES], Bst[kb % STAGES], c, wm, wn);
    }

#pragma unroll
    for (int i = 0; i < 2; i++)
#pragma unroll
        for (int j = 0; j < 4; j++) {
            if (RC) {
#pragma unroll
                for (int t = 0; t < c[i][j].num_elements; t++)
                    c[i][j].x[t] = tf32_rna(c[i][j].x[t]);
            }
            wmma::store_matrix_sync(
                &C[(size_t)(m0 + wm * 32 + i * 16) * ldc + n0 + wn * 64 + j * 16],
                c[i][j], ldc, wmma::mem_row_major);
        }
}

// ---------------- elementwise tf32 rounding pre-pass (float4 grid-stride) ----------------
__global__ void __launch_bounds__(256)
round_tf32_kernel(const float* __restrict__ in, float* __restrict__ out, int n4)
{
    int i = blockIdx.x * 256 + threadIdx.x;
    int stride = gridDim.x * 256;
    for (; i < n4; i += stride) {
        float4 v = reinterpret_cast<const float4*>(in)[i];
        v.x = tf32_rna(v.x); v.y = tf32_rna(v.y);
        v.z = tf32_rna(v.z); v.w = tf32_rna(v.w);
        reinterpret_cast<float4*>(out)[i] = v;
    }
}

// ---------------- row softmax in-place; tf32-rounded probs; zero-fill to 128-block boundary ----
__global__ void __launch_bounds__(256)
softmax_kernel()
{
    const int i = blockIdx.x;
    float* row = g_S + (size_t)i * SEQ;
    const int n = i + 1;
    const float scale = 0.03125f;   // 1/sqrt(1024)
    __shared__ float red[256];

    float m = -1e30f;
    for (int j = threadIdx.x; j < n; j += 256) m = fmaxf(m, row[j] * scale);
    red[threadIdx.x] = m; __syncthreads();
    for (int s = 128; s > 0; s >>= 1) {
        if (threadIdx.x < s) red[threadIdx.x] = fmaxf(red[threadIdx.x], red[threadIdx.x + s]);
        __syncthreads();
    }
    m = red[0]; __syncthreads();

    // Pass 2: compute exp once, store it, accumulate sum
    float sum = 0.0f;
    for (int j = threadIdx.x; j < n; j += 256) {
        float e = __expf(row[j] * scale - m);
        row[j] = e;
        sum += e;
    }
    red[threadIdx.x] = sum; __syncthreads();
    for (int s = 128; s > 0; s >>= 1) {
        if (threadIdx.x < s) red[threadIdx.x] += red[threadIdx.x + s];
        __syncthreads();
    }
    sum = red[0];
    const float inv = 1.0f / sum;

    // Pass 3: normalize + round to tf32 (P is a GEMM operand); zero-fill masked cols
    const int zend = ((i >> 7) + 1) << 7;
    for (int j = threadIdx.x; j < zend; j += 256)
        row[j] = (j < n) ? tf32_rna(row[j] * inv) : 0.0f;
}

extern "C" void kernel_launch(void* const* d_in, const int* in_sizes, int n_in,
                              void* d_out, int out_size)
{
    const float* x = (const float*)d_in[0];   // [4096, 1024]
    const float* W = (const float*)d_in[1];   // [1024, 3072]
    float* out = (float*)d_out;               // [4096, 1024]

    float* qvk; cudaGetSymbolAddress((void**)&qvk, g_qvk);
    float* S;   cudaGetSymbolAddress((void**)&S, g_S);
    float* xr;  cudaGetSymbolAddress((void**)&xr, g_xr);
    float* Wr;  cudaGetSymbolAddress((void**)&Wr, g_Wr);

    // Opt in to >48KB dynamic smem (host-side, idempotent, capture-safe)
    cudaFuncSetAttribute(gemm_tf32<false, false, false, true>,
                         cudaFuncAttributeMaxDynamicSharedMemorySize, SMEM_BYTES);
    cudaFuncSetAttribute(gemm_tf32<true, true, false, false>,
                         cudaFuncAttributeMaxDynamicSharedMemorySize, SMEM_BYTES);
    cudaFuncSetAttribute(gemm_tf32<false, false, true, false>,
                         cudaFuncAttributeMaxDynamicSharedMemorySize, SMEM_BYTES);

    // 0) pre-round x and W to tf32 (numerics identical to per-fragment cvt)
    round_tf32_kernel<<<592, 256>>>(x, xr, SEQ * IND / 4);
    round_tf32_kernel<<<592, 256>>>(W, Wr, IND * TD / 4);

    // 1) qvk = xr @ Wr; epilogue rounds Q/K/V to tf32
    {
        dim3 grid(TD / BN, SEQ / BM);
        gemm_tf32<false, false, false, true><<<grid, NTHREADS, SMEM_BYTES>>>(
            xr, IND, Wr, TD, qvk, TD, IND);
    }
    // 2) S = Q @ K^T (raw scores; scale folded into softmax), lower-tri blocks only
    {
        dim3 grid(SEQ / BN, SEQ / BM);
        gemm_tf32<true, true, false, false><<<grid, NTHREADS, SMEM_BYTES>>>(
            qvk /*Q*/, TD, qvk + 2048 /*K*/, TD, S, SEQ, DHEAD);
    }
    // 3) softmax rows in-place (stores tf32-rounded probs; zero-fills masked cols)
    softmax_kernel<<<SEQ, 256>>>();
    // 4) out = P @ V with causal K truncation per row-block (output NOT rounded)
    {
        dim3 grid(DHEAD / BN, SEQ / BM);
        gemm_tf32<false, false, true, false><<<grid, NTHREADS, SMEM_BYTES>>>(
            S, SEQ, qvk + 1024 /*V*/, TD, out, DHEAD, SEQ);
    }
}

// round 17
// speedup vs baseline: 2.7892x; 2.4380x over previous
#include <cuda_runtime.h>
#include <cuda_fp16.h>
#include <mma.h>
#include <cstdint>
using namespace nvcuda;

#define SEQ   4096
#define IND   1024
#define TD    3072   // 3 * 1024
#define DHEAD 1024

// Scratch (allocation-free rule: __device__ globals)
__device__ float  g_qvk[SEQ * TD];          // fp32 GEMM1 output
__device__ __half g_qvkh[SEQ * TD];         // half copy: Q[0,1024) V[1024,2048) K[2048,3072)
__device__ float  g_S[(size_t)SEQ * SEQ];   // raw scores (fp32)
__device__ __half g_Ph[(size_t)SEQ * SEQ];  // probabilities (half), zero-filled to block boundary
__device__ __half g_xh[SEQ * IND];
__device__ __half g_Wh[IND * TD];

constexpr int BM = 128, BN = 128, BK = 32;
constexpr int NTHREADS = 256;               // 8 warps: 4x2 grid of 32x64 warp tiles
constexpr int STAGES = 3;
constexpr int LDA_H  = 40;                  // halves stride for [x][32] tiles (A, and B when BT)
constexpr int LDB_H  = 136;                 // halves stride for [32][128] row-major B tiles
constexpr int STG_H  = 5120;                // halves per stage buffer (128*40 >= 32*136)
constexpr int SMEM_BYTES = 2 * STAGES * STG_H * 2;  // 61,440 B

// ---------------- cp.async helpers ----------------
__device__ __forceinline__ void cp16(void* dst, const void* src) {
    uint32_t d = (uint32_t)__cvta_generic_to_shared(dst);
    asm volatile("cp.async.cg.shared.global [%0], [%1], 16;\n" :: "r"(d), "l"(src));
}
__device__ __forceinline__ void cp_commit() {
    asm volatile("cp.async.commit_group;\n");
}

// ---------------- tile loaders (async, half) ----------------
// A tile: BM x BK halves -> As[r*LDA_H + c]
// B tile (BT=false, row-major [K][N]): BK x BN -> Bs[k*LDB_H + n]
// B tile (BT=true,  B is [N][K] row-major): BN x BK -> Bs[n*LDA_H + k]  (col-major frag)
template<bool BT>
__device__ __forceinline__ void load_tiles(__half* As, __half* Bs,
    const __half* A, int lda, const __half* B, int ldb,
    int m0, int n0, int k0)
{
    const int tid = threadIdx.x;
#pragma unroll
    for (int t = 0; t < 2; t++) {
        int idx = tid + t * NTHREADS;            // 512 chunks of 8 halves
        int r = idx >> 2, c = (idx & 3) << 3;    // 4 chunks per 32-half row
        cp16(&As[r * LDA_H + c], &A[(size_t)(m0 + r) * lda + k0 + c]);
    }
    if (BT) {
#pragma unroll
        for (int t = 0; t < 2; t++) {
            int idx = tid + t * NTHREADS;
            int r = idx >> 2, c = (idx & 3) << 3;
            cp16(&Bs[r * LDA_H + c], &B[(size_t)(n0 + r) * ldb + k0 + c]);
        }
    } else {
#pragma unroll
        for (int t = 0; t < 2; t++) {
            int idx = tid + t * NTHREADS;
            int r = idx >> 4, c = (idx & 15) << 3; // 16 chunks per 128-half row
            cp16(&Bs[r * LDB_H + c], &B[(size_t)(k0 + r) * ldb + n0 + c]);
        }
    }
}

// ---------------- per-warp fp16 MMA on a staged tile (32x64 warp tile) ----------------
template<bool BT>
__device__ __forceinline__ void mma_stage(const __half* As, const __half* Bs,
    wmma::fragment<wmma::accumulator, 16, 16, 16, float> (&c)[2][4],
    int wm, int wn)
{
#pragma unroll
    for (int kt = 0; kt < BK / 16; kt++) {
        wmma::fragment<wmma::matrix_a, 16, 16, 16, __half, wmma::row_major> a[2];
#pragma unroll
        for (int i = 0; i < 2; i++)
            wmma::load_matrix_sync(a[i], &As[(wm * 32 + i * 16) * LDA_H + kt * 16], LDA_H);
        if constexpr (BT) {
            wmma::fragment<wmma::matrix_b, 16, 16, 16, __half, wmma::col_major> b[4];
#pragma unroll
            for (int j = 0; j < 4; j++)
                wmma::load_matrix_sync(b[j], &Bs[(wn * 64 + j * 16) * LDA_H + kt * 16], LDA_H);
#pragma unroll
            for (int i = 0; i < 2; i++)
#pragma unroll
                for (int j = 0; j < 4; j++)
                    wmma::mma_sync(c[i][j], a[i], b[j], c[i][j]);
        } else {
            wmma::fragment<wmma::matrix_b, 16, 16, 16, __half, wmma::row_major> b[4];
#pragma unroll
            for (int j = 0; j < 4; j++)
                wmma::load_matrix_sync(b[j], &Bs[(kt * 16) * LDB_H + wn * 64 + j * 16], LDB_H);
#pragma unroll
            for (int i = 0; i < 2; i++)
#pragma unroll
                for (int j = 0; j < 4; j++)
                    wmma::mma_sync(c[i][j], a[i], b[j], c[i][j]);
        }
    }
}

// ---------------- 3-stage pipelined 128x128x32 fp16 GEMM, one barrier per k-iter ------
// BT: B is [N][K] row-major (col-major fragments)   -- for Q@K^T
// CSKIP: skip blocks fully above the diagonal       -- for Q@K^T
// CK: causal: remap by (heavy-first) + truncate K   -- for P@V
template<bool BT, bool CSKIP, bool CK>
__global__ void __launch_bounds__(NTHREADS, 1)
gemm_h(const __half* __restrict__ A, int lda,
       const __half* __restrict__ B, int ldb,
       float* __restrict__ C, int ldc, int K)
{
    const int bx = blockIdx.x, by = blockIdx.y;
    if (CSKIP && bx > by) return;
    // Heavy-first remap for causal-truncated GEMM (load balance across waves)
    const int byw = CK ? ((int)gridDim.y - 1 - by) : by;

    extern __shared__ __half smem_h[];
    __half* Ast[STAGES]; __half* Bst[STAGES];
#pragma unroll
    for (int s = 0; s < STAGES; s++) {
        Ast[s] = smem_h + s * STG_H;
        Bst[s] = smem_h + (STAGES + s) * STG_H;
    }

    const int m0 = byw * BM, n0 = bx * BN;
    const int Keff = CK ? (byw + 1) * BM : K;
    const int NK = Keff / BK;

    wmma::fragment<wmma::accumulator, 16, 16, 16, float> c[2][4];
#pragma unroll
    for (int i = 0; i < 2; i++)
#pragma unroll
        for (int j = 0; j < 4; j++)
            wmma::fill_fragment(c[i][j], 0.0f);

    const int warp = threadIdx.x >> 5;
    const int wm = warp >> 1, wn = warp & 1;  // 4x2 warps, 32x64 per-warp tile

    load_tiles<BT>(Ast[0], Bst[0], A, lda, B, ldb, m0, n0, 0);
    cp_commit();
    if (NK > 1) {
        load_tiles<BT>(Ast[1], Bst[1], A, lda, B, ldb, m0, n0, BK);
        cp_commit();
    }

    for (int kb = 0; kb < NK; kb++) {
        if (kb + 1 < NK) asm volatile("cp.async.wait_group 1;\n");
        else             asm volatile("cp.async.wait_group 0;\n");
        // Single barrier: stage kb resident for all; stage (kb+2)%3==(kb-1)%3 consumed.
        __syncthreads();
        if (kb + 2 < NK) {
            load_tiles<BT>(Ast[(kb + 2) % STAGES], Bst[(kb + 2) % STAGES],
                           A, lda, B, ldb, m0, n0, (kb + 2) * BK);
            cp_commit();
        }
        mma_stage<BT>(Ast[kb % STAGES], Bst[kb % STAGES], c, wm, wn);
    }

#pragma unroll
    for (int i = 0; i < 2; i++)
#pragma unroll
        for (int j = 0; j < 4; j++)
            wmma::store_matrix_sync(
                &C[(size_t)(m0 + wm * 32 + i * 16) * ldc + n0 + wn * 64 + j * 16],
                c[i][j], ldc, wmma::mem_row_major);
}

// ---------------- fp32 -> fp16 conversion (8 elems/thread/iter, 16B stores) ----------
__global__ void __launch_bounds__(256)
f32_to_f16_kernel(const float* __restrict__ in, __half* __restrict__ out, int n8)
{
    int i = blockIdx.x * 256 + threadIdx.x;
    const int stride = gridDim.x * 256;
    for (; i < n8; i += stride) {
        const float4* p = reinterpret_cast<const float4*>(in) + 2 * (size_t)i;
        float4 v0 = p[0], v1 = p[1];
        __half2 h0 = __floats2half2_rn(v0.x, v0.y);
        __half2 h1 = __floats2half2_rn(v0.z, v0.w);
        __half2 h2 = __floats2half2_rn(v1.x, v1.y);
        __half2 h3 = __floats2half2_rn(v1.z, v1.w);
        uint4 u;
        u.x = *reinterpret_cast<uint32_t*>(&h0);
        u.y = *reinterpret_cast<uint32_t*>(&h1);
        u.z = *reinterpret_cast<uint32_t*>(&h2);
        u.w = *reinterpret_cast<uint32_t*>(&h3);
        reinterpret_cast<uint4*>(out)[i] = u;
    }
}

// ------- row softmax: read fp32 scores, write half probs; zero-fill to 128-boundary ----
__global__ void __launch_bounds__(256)
softmax_kernel()
{
    const int i = blockIdx.x;
    float*  rowf = g_S  + (size_t)i * SEQ;
    __half* rowh = g_Ph + (size_t)i * SEQ;
    const int n = i + 1;
    const float scale = 0.03125f;   // 1/sqrt(1024)
    __shared__ float red[256];

    float m = -1e30f;
    for (int j = threadIdx.x; j < n; j += 256) m = fmaxf(m, rowf[j] * scale);
    red[threadIdx.x] = m; __syncthreads();
    for (int s = 128; s > 0; s >>= 1) {
        if (threadIdx.x < s) red[threadIdx.x] = fmaxf(red[threadIdx.x], red[threadIdx.x + s]);
        __syncthreads();
    }
    m = red[0]; __syncthreads();

    float sum = 0.0f;
    for (int j = threadIdx.x; j < n; j += 256) {
        float e = __expf(rowf[j] * scale - m);
        rowf[j] = e;
        sum += e;
    }
    red[threadIdx.x] = sum; __syncthreads();
    for (int s = 128; s > 0; s >>= 1) {
        if (threadIdx.x < s) red[threadIdx.x] += red[threadIdx.x + s];
        __syncthreads();
    }
    sum = red[0];
    const float inv = 1.0f / sum;

    const int zend = ((i >> 7) + 1) << 7;   // this row's 128-block boundary
    for (int j = threadIdx.x; j < zend; j += 256)
        rowh[j] = __float2half((j < n) ? rowf[j] * inv : 0.0f);
}

extern "C" void kernel_launch(void* const* d_in, const int* in_sizes, int n_in,
                              void* d_out, int out_size)
{
    const float* x = (const float*)d_in[0];   // [4096, 1024]
    const float* W = (const float*)d_in[1];   // [1024, 3072]
    float* out = (float*)d_out;               // [4096, 1024]

    float*  qvk;  cudaGetSymbolAddress((void**)&qvk,  g_qvk);
    __half* qvkh; cudaGetSymbolAddress((void**)&qvkh, g_qvkh);
    float*  S;    cudaGetSymbolAddress((void**)&S,    g_S);
    __half* Ph;   cudaGetSymbolAddress((void**)&Ph,   g_Ph);
    __half* xh;   cudaGetSymbolAddress((void**)&xh,   g_xh);
    __half* Wh;   cudaGetSymbolAddress((void**)&Wh,   g_Wh);

    cudaFuncSetAttribute(gemm_h<false, false, false>,
                         cudaFuncAttributeMaxDynamicSharedMemorySize, SMEM_BYTES);
    cudaFuncSetAttribute(gemm_h<true, true, false>,
                         cudaFuncAttributeMaxDynamicSharedMemorySize, SMEM_BYTES);
    cudaFuncSetAttribute(gemm_h<false, false, true>,
                         cudaFuncAttributeMaxDynamicSharedMemorySize, SMEM_BYTES);

    // 0) convert inputs to half
    f32_to_f16_kernel<<<592, 256>>>(x, xh, SEQ * IND / 8);
    f32_to_f16_kernel<<<592, 256>>>(W, Wh, IND * TD / 8);

    // 1) qvk = xh @ Wh  (fp32 out), then half copy for downstream GEMMs
    gemm_h<false, false, false><<<dim3(TD / BN, SEQ / BM), NTHREADS, SMEM_BYTES>>>(
        xh, IND, Wh, TD, qvk, TD, IND);
    f32_to_f16_kernel<<<592, 256>>>(qvk, qvkh, SEQ * TD / 8);

    // 2) S = Q @ K^T (raw; scale folded into softmax), lower-tri blocks only
    gemm_h<true, true, false><<<dim3(SEQ / BN, SEQ / BM), NTHREADS, SMEM_BYTES>>>(
        qvkh /*Q*/, TD, qvkh + 2048 /*K*/, TD, S, SEQ, DHEAD);

    // 3) softmax rows -> half P (zero-filled to 128-block boundary)
    softmax_kernel<<<SEQ, 256>>>();

    // 4) out = P @ V, causal K truncation, heavy-blocks-first schedule
    gemm_h<false, false, true><<<dim3(DHEAD / BN, SEQ / BM), NTHREADS, SMEM_BYTES>>>(
        Ph, SEQ, qvkh + 1024 /*V*/, TD, out, DHEAD, SEQ);
}